// round 1
// baseline (speedup 1.0000x reference)
#include <cuda_runtime.h>

#define B_   256
#define C_   2048
#define K_   18
#define HW_  192
#define TPB  256
#define CPT  2   // c-rows per thread

// Packed fp32x2 FMA: acc = m * v + acc  (elementwise on both lanes).
// Only reachable via PTX fma.rn.f32x2 (ptxas never auto-fuses).
__device__ __forceinline__ void ffma2(float2& acc, float2 m, float2 v) {
    unsigned long long a  = *reinterpret_cast<unsigned long long*>(&acc);
    unsigned long long mm = *reinterpret_cast<unsigned long long*>(&m);
    unsigned long long vv = *reinterpret_cast<unsigned long long*>(&v);
    asm("fma.rn.f32x2 %0, %1, %2, %0;" : "+l"(a) : "l"(mm), "l"(vv));
    acc = *reinterpret_cast<float2*>(&a);
}

__global__ __launch_bounds__(TPB)
void pgfa_kernel(const float* __restrict__ feat,
                 const float* __restrict__ masks,
                 const float* __restrict__ pgf,
                 float* __restrict__ out)
{
    __shared__ float s_m[K_ * HW_];   // 13,824 bytes: masks for this b

    const int b   = blockIdx.y;
    const int tid = threadIdx.x;

    // Stage masks[b] into smem with float4 loads (coalesced, 864 float4s).
    {
        const float4* msrc = reinterpret_cast<const float4*>(masks + (size_t)b * K_ * HW_);
        float4*       mdst = reinterpret_cast<float4*>(s_m);
        #pragma unroll 2
        for (int i = tid; i < K_ * HW_ / 4; i += TPB) mdst[i] = msrc[i];
    }
    __syncthreads();

    const int c0 = blockIdx.x * (TPB * CPT) + tid;

    float2 acc[CPT][K_];
    #pragma unroll
    for (int j = 0; j < CPT; j++)
        #pragma unroll
        for (int k = 0; k < K_; k++) acc[j][k] = make_float2(0.f, 0.f);

    const float4* frow[CPT];
    #pragma unroll
    for (int j = 0; j < CPT; j++)
        frow[j] = reinterpret_cast<const float4*>(
            feat + ((size_t)b * C_ + (size_t)(c0 + j * TPB)) * HW_);

    // Main loop: 48 float4 positions along HW.
    #pragma unroll 2
    for (int p = 0; p < HW_ / 4; p++) {
        float4 v[CPT];
        #pragma unroll
        for (int j = 0; j < CPT; j++) v[j] = frow[j][p];

        #pragma unroll
        for (int k = 0; k < K_; k++) {
            // one LDS.128 per k per float4-position (broadcast across the warp)
            float4 m4 = *reinterpret_cast<const float4*>(&s_m[k * HW_ + p * 4]);
            float2 mlo = make_float2(m4.x, m4.y);
            float2 mhi = make_float2(m4.z, m4.w);
            #pragma unroll
            for (int j = 0; j < CPT; j++) {
                ffma2(acc[j][k], mlo, make_float2(v[j].x, v[j].y));
                ffma2(acc[j][k], mhi, make_float2(v[j].z, v[j].w));
            }
        }
    }

    // Epilogue: mean (1/192), max over k, write both output halves.
    const float inv = 1.0f / (float)HW_;
    #pragma unroll
    for (int j = 0; j < CPT; j++) {
        const int c = c0 + j * TPB;
        float mx = -3.402823466e+38f;
        #pragma unroll
        for (int k = 0; k < K_; k++) {
            float s = acc[j][k].x + acc[j][k].y;
            mx = fmaxf(mx, s);
        }
        const size_t orow = (size_t)b * (2 * C_);
        out[orow + C_ + c] = mx * inv;                 // pooled-max half
        out[orow + c]      = pgf[(size_t)b * C_ + c];  // global-feature half
    }
}

extern "C" void kernel_launch(void* const* d_in, const int* in_sizes, int n_in,
                              void* d_out, int out_size)
{
    const float* feat  = (const float*)d_in[0];
    const float* masks = (const float*)d_in[1];
    const float* pgf   = (const float*)d_in[2];
    float*       out   = (float*)d_out;

    dim3 grid(C_ / (TPB * CPT), B_);   // (4, 256) = 1024 blocks
    pgfa_kernel<<<grid, TPB>>>(feat, masks, pgf, out);
}

// round 2
// speedup vs baseline: 1.4522x; 1.4522x over previous
#include <cuda_runtime.h>
#include <cstdint>

#define B_     256
#define C_     2048
#define K_     18
#define HW_    192
#define TPB    256
#define CPT    2
#define CTILE  (TPB*CPT)         // 512 c-rows per block
#define CHUNK  16                // hw positions staged per phase
#define NCH    (HW_/CHUNK)       // 12 phases
#define FSTRIDE 20               // padded row stride in words (16 data + 4 pad)
// smem: masks [18*192] + 2 feat buffers [512*FSTRIDE]
#define SM_MASK_WORDS (K_*HW_)                 // 3456
#define SM_FEAT_WORDS (CTILE*FSTRIDE)          // 10240
#define SM_TOTAL_BYTES ((SM_MASK_WORDS + 2*SM_FEAT_WORDS)*4)   // 95744

// Packed fp32x2 FMA (only reachable via PTX; ptxas never auto-fuses).
__device__ __forceinline__ void ffma2(float2& acc, float2 m, float2 v) {
    unsigned long long a  = *reinterpret_cast<unsigned long long*>(&acc);
    unsigned long long mm = *reinterpret_cast<unsigned long long*>(&m);
    unsigned long long vv = *reinterpret_cast<unsigned long long*>(&v);
    asm("fma.rn.f32x2 %0, %1, %2, %0;" : "+l"(a) : "l"(mm), "l"(vv));
    acc = *reinterpret_cast<float2*>(&a);
}

__device__ __forceinline__ uint32_t s2u(const void* p) {
    uint32_t a;
    asm("{ .reg .u64 t; cvta.to.shared.u64 t, %1; cvt.u32.u64 %0, t; }"
        : "=r"(a) : "l"(p));
    return a;
}
__device__ __forceinline__ void cpasync16(uint32_t s, const void* g) {
    asm volatile("cp.async.cg.shared.global [%0], [%1], 16;" :: "r"(s), "l"(g));
}
__device__ __forceinline__ void cp_commit() {
    asm volatile("cp.async.commit_group;" ::: "memory");
}
template <int N>
__device__ __forceinline__ void cp_wait() {
    asm volatile("cp.async.wait_group %0;" :: "n"(N) : "memory");
}

extern __shared__ float smem[];

__global__ __launch_bounds__(TPB, 2)
void pgfa_kernel(const float* __restrict__ feat,
                 const float* __restrict__ masks,
                 const float* __restrict__ pgf,
                 float* __restrict__ out)
{
    float* s_m = smem;                          // [K_*HW_]
    float* s_f0 = smem + SM_MASK_WORDS;         // feat buffer 0
    float* s_f1 = s_f0 + SM_FEAT_WORDS;         // feat buffer 1

    const int b    = blockIdx.y;
    const int tid  = threadIdx.x;
    const int cbase = blockIdx.x * CTILE;

    // ---- stage masks[b] (coalesced float4) ----
    {
        const float4* msrc = reinterpret_cast<const float4*>(masks + (size_t)b * K_ * HW_);
        float4*       mdst = reinterpret_cast<float4*>(s_m);
        #pragma unroll
        for (int i = tid; i < K_ * HW_ / 4; i += TPB) mdst[i] = msrc[i];
    }

    const float* frow_base = feat + ((size_t)b * C_ + cbase) * HW_;

    // issue cp.async for chunk `ch` into buffer `dst`
    // per chunk: 512 rows x 16 floats = 2048 float4; 8 per thread
    auto issue_chunk = [&](float* dst, int ch) {
        uint32_t sbase = s2u(dst);
        #pragma unroll
        for (int t = 0; t < 8; t++) {
            int flat = t * TPB + tid;          // 0..2047
            int row  = flat >> 2;              // 4 float4 per row
            int off  = flat & 3;
            const float* g = frow_base + (size_t)row * HW_ + ch * CHUNK + off * 4;
            uint32_t s = sbase + (row * FSTRIDE + off * 4) * 4;
            cpasync16(s, g);
        }
        cp_commit();
    };

    float2 acc[CPT][K_];
    #pragma unroll
    for (int j = 0; j < CPT; j++)
        #pragma unroll
        for (int k = 0; k < K_; k++) acc[j][k] = make_float2(0.f, 0.f);

    issue_chunk(s_f0, 0);

    #pragma unroll 1
    for (int ch = 0; ch < NCH; ch++) {
        float* cur = (ch & 1) ? s_f1 : s_f0;
        float* nxt = (ch & 1) ? s_f0 : s_f1;

        if (ch + 1 < NCH) { issue_chunk(nxt, ch + 1); cp_wait<1>(); }
        else              { cp_wait<0>(); }
        __syncthreads();   // chunk `ch` data (and masks, first iter) visible

        // ---- compute on cur: 4 float4-positions ----
        #pragma unroll
        for (int p = 0; p < CHUNK / 4; p++) {
            float4 v[CPT];
            #pragma unroll
            for (int j = 0; j < CPT; j++) {
                int row = tid + j * TPB;
                v[j] = *reinterpret_cast<const float4*>(cur + row * FSTRIDE + p * 4);
            }
            const float* mptr = s_m + ch * CHUNK + p * 4;
            #pragma unroll
            for (int k = 0; k < K_; k++) {
                float4 m4 = *reinterpret_cast<const float4*>(mptr + k * HW_);
                float2 mlo = make_float2(m4.x, m4.y);
                float2 mhi = make_float2(m4.z, m4.w);
                #pragma unroll
                for (int j = 0; j < CPT; j++) {
                    ffma2(acc[j][k], mlo, make_float2(v[j].x, v[j].y));
                    ffma2(acc[j][k], mhi, make_float2(v[j].z, v[j].w));
                }
            }
        }
        __syncthreads();   // all reads of `cur` done before it is refilled
    }

    // ---- epilogue: mean, max over k, write both halves ----
    const float inv = 1.0f / (float)HW_;
    #pragma unroll
    for (int j = 0; j < CPT; j++) {
        const int c = cbase + tid + j * TPB;
        float mx = -3.402823466e+38f;
        #pragma unroll
        for (int k = 0; k < K_; k++) {
            float s = acc[j][k].x + acc[j][k].y;
            mx = fmaxf(mx, s);
        }
        const size_t orow = (size_t)b * (2 * C_);
        out[orow + C_ + c] = mx * inv;
        out[orow + c]      = pgf[(size_t)b * C_ + c];
    }
}

extern "C" void kernel_launch(void* const* d_in, const int* in_sizes, int n_in,
                              void* d_out, int out_size)
{
    const float* feat  = (const float*)d_in[0];
    const float* masks = (const float*)d_in[1];
    const float* pgf   = (const float*)d_in[2];
    float*       out   = (float*)d_out;

    cudaFuncSetAttribute(pgfa_kernel,
                         cudaFuncAttributeMaxDynamicSharedMemorySize,
                         SM_TOTAL_BYTES);

    dim3 grid(C_ / CTILE, B_);   // (4, 256)
    pgfa_kernel<<<grid, TPB, SM_TOTAL_BYTES>>>(feat, masks, pgf, out);
}